// round 1
// baseline (speedup 1.0000x reference)
#include <cuda_runtime.h>
#include <cuda_bf16.h>
#include <cstdint>
#include <math.h>

// Problem constants
#define BC   16      // BATCH * CELLS
#define TT   2048    // sequence length
#define DD   256     // feature dim
#define BB   2
#define CC   8

#define SD   260     // padded smem row stride (floats) for 256-wide tiles
#define PSD  68      // padded smem row stride for 64-wide P tile

// fp32 scratch for qkv = LN(x) @ gate : [BC*T, D]
__device__ float g_qkv[(size_t)BC * TT * DD];

// ---------------------------------------------------------------------------
// Kernel 1: fused LayerNorm + GEMM (nx @ gate) -> g_qkv
// Block: 256 threads, handles 64 token rows. Grid: BC*T/64 = 512.
// ---------------------------------------------------------------------------
__global__ __launch_bounds__(256) void ln_gemm_kernel(
    const float* __restrict__ x, const float* __restrict__ gate)
{
    extern __shared__ float sm[];
    float* nxs = sm;            // 64 x SD
    float* gs  = sm + 64 * SD;  // 64 x SD

    const int tid = threadIdx.x;
    const int row0 = blockIdx.x * 64;   // global token row base

    // --- coalesced load of 64x256 x-tile into padded smem ---
    const float4* xg = (const float4*)(x + (size_t)row0 * DD);
    for (int i = tid; i < 4096; i += 256) {
        int r = i >> 6, c = i & 63;
        *(float4*)(nxs + r * SD + c * 4) = xg[i];
    }
    __syncthreads();

    // --- LayerNorm: 4 threads per row ---
    {
        const int r = tid >> 2;
        const int sub = tid & 3;
        float s = 0.f, sq = 0.f;
        #pragma unroll
        for (int i = 0; i < 16; ++i) {
            float4 v = *(float4*)(nxs + r * SD + (sub + 4 * i) * 4);
            s  += v.x + v.y + v.z + v.w;
            sq += v.x * v.x + v.y * v.y + v.z * v.z + v.w * v.w;
        }
        #pragma unroll
        for (int off = 1; off < 4; off <<= 1) {
            s  += __shfl_xor_sync(0xffffffffu, s,  off);
            sq += __shfl_xor_sync(0xffffffffu, sq, off);
        }
        const float mean = s * (1.f / 256.f);
        const float var  = sq * (1.f / 256.f) - mean * mean;
        const float rstd = rsqrtf(var + 1e-5f);
        #pragma unroll
        for (int i = 0; i < 16; ++i) {
            float4* p = (float4*)(nxs + r * SD + (sub + 4 * i) * 4);
            float4 v = *p;
            v.x = (v.x - mean) * rstd; v.y = (v.y - mean) * rstd;
            v.z = (v.z - mean) * rstd; v.w = (v.w - mean) * rstd;
            *p = v;
        }
    }
    __syncthreads();

    // --- GEMM: out[64 x 256] = nx[64 x 256] @ gate[256 x 256] ---
    const int ty = tid >> 4;   // 0..15 : row group (4 rows each)
    const int tx = tid & 15;   // 0..15 : col group
    float4 acc[4][4];          // rows ty*4+r ; cols j*64 + tx*4 (+0..3)
    #pragma unroll
    for (int r = 0; r < 4; ++r)
        #pragma unroll
        for (int j = 0; j < 4; ++j)
            acc[r][j] = make_float4(0.f, 0.f, 0.f, 0.f);

    for (int kt = 0; kt < 4; ++kt) {
        // load gate rows [kt*64, kt*64+64) x 256 into gs
        const float4* gg = (const float4*)(gate + (size_t)kt * 64 * DD);
        for (int i = tid; i < 4096; i += 256) {
            int r = i >> 6, c = i & 63;
            *(float4*)(gs + r * SD + c * 4) = gg[i];
        }
        __syncthreads();

        #pragma unroll 4
        for (int kk = 0; kk < 64; ++kk) {
            float a[4];
            #pragma unroll
            for (int r = 0; r < 4; ++r)
                a[r] = nxs[(ty * 4 + r) * SD + kt * 64 + kk];
            #pragma unroll
            for (int j = 0; j < 4; ++j) {
                float4 g4 = *(float4*)(gs + kk * SD + j * 64 + tx * 4);
                #pragma unroll
                for (int r = 0; r < 4; ++r) {
                    acc[r][j].x = fmaf(a[r], g4.x, acc[r][j].x);
                    acc[r][j].y = fmaf(a[r], g4.y, acc[r][j].y);
                    acc[r][j].z = fmaf(a[r], g4.z, acc[r][j].z);
                    acc[r][j].w = fmaf(a[r], g4.w, acc[r][j].w);
                }
            }
        }
        __syncthreads();
    }

    // write qkv
    #pragma unroll
    for (int r = 0; r < 4; ++r) {
        size_t rowg = (size_t)(row0 + ty * 4 + r);
        #pragma unroll
        for (int j = 0; j < 4; ++j)
            *(float4*)(g_qkv + rowg * DD + j * 64 + tx * 4) = acc[r][j];
    }
}

// ---------------------------------------------------------------------------
// Kernel 2: causal flash attention (fp32) : y = x + softmax(qkv qkv^T * s) qkv
// Block: 256 threads handles one (bc, 64-query tile). Grid: 16*32 = 512.
// Heavy tiles (large qt) are scheduled first via reversed mapping.
// ---------------------------------------------------------------------------
__global__ __launch_bounds__(256) void attn_kernel(
    const float* __restrict__ x, float* __restrict__ y)
{
    extern __shared__ float sm[];
    float* Qs = sm;                 // 64 x SD
    float* Ks = sm + 64 * SD;       // 64 x SD
    float* Ps = sm + 128 * SD;      // 64 x PSD

    const int bid = blockIdx.x;
    const int bc = bid & 15;
    const int qt = ((int)(gridDim.x >> 4)) - 1 - (bid >> 4);  // 31..0
    const int q0 = qt * 64;
    const int tid = threadIdx.x;
    const int ty = tid >> 4;   // 0..15 (4 q-rows each)
    const int tx = tid & 15;
    const float scale = 0.0625f;   // 256^-0.5

    // load Q tile
    const float4* qg = (const float4*)(g_qkv + ((size_t)(bc * TT + q0)) * DD);
    for (int i = tid; i < 4096; i += 256) {
        int r = i >> 6, c = i & 63;
        *(float4*)(Qs + r * SD + c * 4) = qg[i];
    }

    float4 acc[4][4];   // O accum: rows ty*4+r, cols j*64 + tx*4
    #pragma unroll
    for (int r = 0; r < 4; ++r)
        #pragma unroll
        for (int j = 0; j < 4; ++j)
            acc[r][j] = make_float4(0.f, 0.f, 0.f, 0.f);
    float mi[4], li[4];
    #pragma unroll
    for (int r = 0; r < 4; ++r) { mi[r] = -1e30f; li[r] = 0.f; }

    for (int kt = 0; kt <= qt; ++kt) {
        __syncthreads();   // protect Ks (read in previous O phase)
        const float4* kg = (const float4*)(g_qkv + ((size_t)(bc * TT + kt * 64)) * DD);
        for (int i = tid; i < 4096; i += 256) {
            int r = i >> 6, c = i & 63;
            *(float4*)(Ks + r * SD + c * 4) = kg[i];
        }
        __syncthreads();

        // ---- S = Q K^T : thread owns rows ty*4+r, k-cols c*16+tx ----
        float s[4][4];
        #pragma unroll
        for (int r = 0; r < 4; ++r)
            #pragma unroll
            for (int c = 0; c < 4; ++c) s[r][c] = 0.f;

        #pragma unroll 4
        for (int d0 = 0; d0 < 256; d0 += 4) {
            float4 qv[4], kv[4];
            #pragma unroll
            for (int r = 0; r < 4; ++r)
                qv[r] = *(float4*)(Qs + (ty * 4 + r) * SD + d0);
            #pragma unroll
            for (int c = 0; c < 4; ++c)
                kv[c] = *(float4*)(Ks + (c * 16 + tx) * SD + d0);
            #pragma unroll
            for (int r = 0; r < 4; ++r)
                #pragma unroll
                for (int c = 0; c < 4; ++c) {
                    s[r][c] = fmaf(qv[r].x, kv[c].x, s[r][c]);
                    s[r][c] = fmaf(qv[r].y, kv[c].y, s[r][c]);
                    s[r][c] = fmaf(qv[r].z, kv[c].z, s[r][c]);
                    s[r][c] = fmaf(qv[r].w, kv[c].w, s[r][c]);
                }
        }

        // scale + causal mask (only diagonal tile needs mask)
        if (kt == qt) {
            #pragma unroll
            for (int r = 0; r < 4; ++r) {
                int qrow = ty * 4 + r;       // local; global offset identical
                #pragma unroll
                for (int c = 0; c < 4; ++c) {
                    int kcol = c * 16 + tx;
                    s[r][c] = (kcol > qrow) ? -1e30f : s[r][c] * scale;
                }
            }
        } else {
            #pragma unroll
            for (int r = 0; r < 4; ++r)
                #pragma unroll
                for (int c = 0; c < 4; ++c) s[r][c] *= scale;
        }

        // ---- online softmax ----
        #pragma unroll
        for (int r = 0; r < 4; ++r) {
            float rmax = s[r][0];
            #pragma unroll
            for (int c = 1; c < 4; ++c) rmax = fmaxf(rmax, s[r][c]);
            #pragma unroll
            for (int off = 8; off >= 1; off >>= 1)
                rmax = fmaxf(rmax, __shfl_xor_sync(0xffffffffu, rmax, off));
            float mnew = fmaxf(mi[r], rmax);
            float alpha = __expf(mi[r] - mnew);
            mi[r] = mnew;

            float rs = 0.f;
            #pragma unroll
            for (int c = 0; c < 4; ++c) {
                float p = __expf(s[r][c] - mnew);
                s[r][c] = p;
                rs += p;
            }
            #pragma unroll
            for (int off = 8; off >= 1; off >>= 1)
                rs += __shfl_xor_sync(0xffffffffu, rs, off);
            li[r] = li[r] * alpha + rs;

            // rescale existing O
            #pragma unroll
            for (int j = 0; j < 4; ++j) {
                acc[r][j].x *= alpha; acc[r][j].y *= alpha;
                acc[r][j].z *= alpha; acc[r][j].w *= alpha;
            }
        }

        // store P tile
        #pragma unroll
        for (int r = 0; r < 4; ++r)
            #pragma unroll
            for (int c = 0; c < 4; ++c)
                Ps[(ty * 4 + r) * PSD + c * 16 + tx] = s[r][c];
        __syncthreads();

        // ---- O += P @ V  (V == Ks) ----
        #pragma unroll 8
        for (int k = 0; k < 64; ++k) {
            float p[4];
            #pragma unroll
            for (int r = 0; r < 4; ++r)
                p[r] = Ps[(ty * 4 + r) * PSD + k];
            #pragma unroll
            for (int j = 0; j < 4; ++j) {
                float4 v = *(float4*)(Ks + k * SD + j * 64 + tx * 4);
                #pragma unroll
                for (int r = 0; r < 4; ++r) {
                    acc[r][j].x = fmaf(p[r], v.x, acc[r][j].x);
                    acc[r][j].y = fmaf(p[r], v.y, acc[r][j].y);
                    acc[r][j].z = fmaf(p[r], v.z, acc[r][j].z);
                    acc[r][j].w = fmaf(p[r], v.w, acc[r][j].w);
                }
            }
        }
    }

    // ---- epilogue: y = x + O / l ----
    #pragma unroll
    for (int r = 0; r < 4; ++r) {
        float inv = 1.f / li[r];
        size_t rowg = (size_t)(bc * TT + q0 + ty * 4 + r);
        #pragma unroll
        for (int j = 0; j < 4; ++j) {
            float4 xr = *(const float4*)(x + rowg * DD + j * 64 + tx * 4);
            float4 o;
            o.x = xr.x + acc[r][j].x * inv;
            o.y = xr.y + acc[r][j].y * inv;
            o.z = xr.z + acc[r][j].z * inv;
            o.w = xr.w + acc[r][j].w * inv;
            *(float4*)(y + rowg * DD + j * 64 + tx * 4) = o;
        }
    }
}

// ---------------------------------------------------------------------------
// Kernel 3: cross-cell mixing + pulse, in-place on y (= d_out).
// Each thread owns one (b, t, d) across all 8 cells -> race-free in-place.
// ---------------------------------------------------------------------------
__global__ __launch_bounds__(256) void mix_kernel(
    const float* __restrict__ inhibit, const float* __restrict__ phases,
    const float* __restrict__ ambition, float* __restrict__ y)
{
    __shared__ float inh[64];
    __shared__ float ph[8];
    __shared__ float am[8];
    if (threadIdx.x < 64) inh[threadIdx.x] = inhibit[threadIdx.x];
    if (threadIdx.x < 8) {
        ph[threadIdx.x] = phases[threadIdx.x];
        am[threadIdx.x] = ambition[threadIdx.x];
    }
    __syncthreads();

    const int idx = blockIdx.x * 256 + threadIdx.x;   // over B*T*D = 2^20
    const int d = idx & 255;
    const int t = (idx >> 8) & (TT - 1);
    const int b = idx >> 19;
    const size_t cstride = (size_t)TT * DD;
    const size_t base = ((size_t)b * CC * TT + t) * DD + d;

    float v[CC];
    #pragma unroll
    for (int c = 0; c < CC; ++c) v[c] = y[base + c * cstride];

    #pragma unroll
    for (int k = 0; k < CC; ++k) {
        float comp = 0.f;
        #pragma unroll
        for (int c = 0; c < CC; ++c) comp = fmaf(v[c], inh[c * CC + k], comp);
        float xv = v[k] + tanhf(comp);
        float out = xv + 0.02f * sinf(xv * am[k] + ph[k]);
        y[base + k * cstride] = out;
    }
}

// ---------------------------------------------------------------------------
extern "C" void kernel_launch(void* const* d_in, const int* in_sizes, int n_in,
                              void* d_out, int out_size)
{
    const float* x        = (const float*)d_in[0];
    // d_in[1] = mask (boolean causal triu) -- computed analytically, unused
    const float* gate     = (const float*)d_in[2];
    const float* inhibit  = (const float*)d_in[3];
    const float* phases   = (const float*)d_in[4];
    const float* ambition = (const float*)d_in[5];
    float* out = (float*)d_out;

    const int smem1 = 128 * SD * 4;               // 133,120 B
    const int smem2 = (128 * SD + 64 * PSD) * 4;  // 150,528 B
    cudaFuncSetAttribute(ln_gemm_kernel, cudaFuncAttributeMaxDynamicSharedMemorySize, smem1);
    cudaFuncSetAttribute(attn_kernel,    cudaFuncAttributeMaxDynamicSharedMemorySize, smem2);

    ln_gemm_kernel<<<(BC * TT) / 64, 256, smem1>>>(x, gate);
    attn_kernel<<<BC * (TT / 64), 256, smem2>>>(x, out);
    mix_kernel<<<(BB * TT * DD) / 256, 256>>>(inhibit, phases, ambition, out);
}